// round 2
// baseline (speedup 1.0000x reference)
#include <cuda_runtime.h>
#include <cstdint>

// Problem constants
#define NPIX   65536        // H*W = 256*256
#define BATCH  2
#define MROWS  524288       // 4 shifts * BATCH * NPIX
#define K1PAD  400          // 386 padded to multiple of 16

// Static scratch (each < 2GB). Feature-major activations [K, M].
__device__ float g_X[512u * 524288u];     // X / act2 buffer
__device__ float g_bufA[512u * 524288u];  // act1 lo / act3
__device__ float g_bufB[512u * 524288u];  // act1 hi / act4
__device__ float g_W[1097728];            // tf32-rounded padded weights

// ---------------- helpers ----------------
__device__ __forceinline__ float tf32r(float x) {
    uint32_t u;
    asm("cvt.rna.tf32.f32 %0, %1;" : "=r"(u) : "f"(x));
    return __uint_as_float(u);
}

__device__ __forceinline__ void mma_tf32(float c[4], const uint32_t a[4], const uint32_t b[2]) {
    asm volatile(
        "mma.sync.aligned.m16n8k8.row.col.f32.tf32.tf32.f32 "
        "{%0,%1,%2,%3}, {%4,%5,%6,%7}, {%8,%9}, {%0,%1,%2,%3};\n"
        : "+f"(c[0]), "+f"(c[1]), "+f"(c[2]), "+f"(c[3])
        : "r"(a[0]), "r"(a[1]), "r"(a[2]), "r"(a[3]), "r"(b[0]), "r"(b[1]));
}

__device__ __forceinline__ void cpasync16(void* smem, const void* gmem) {
    uint32_t s = (uint32_t)__cvta_generic_to_shared(smem);
    asm volatile("cp.async.cg.shared.global [%0], [%1], 16;\n" :: "r"(s), "l"(gmem));
}

// ---------------- weight prep: pad K and round to tf32 ----------------
__global__ void k_prep(const float* __restrict__ w, float* __restrict__ dst,
                       int Ksrc, int Kdst, int No) {
    int i = blockIdx.x * 256 + threadIdx.x;
    int total = Kdst * No;
    if (i >= total) return;
    int k = i / No;
    int j = i - k * No;
    float v = (k < Ksrc) ? w[(size_t)k * No + j] : 0.f;
    dst[i] = tf32r(v);
}

// ---------------- build X [400, M] feature-major, tf32-rounded ----------------
__global__ void k_build(const float* __restrict__ feat, const float* __restrict__ coord,
                        const float* __restrict__ hr, const float* __restrict__ lr,
                        float* __restrict__ X) {
    int n = blockIdx.x * 256 + threadIdx.x;
    int b = blockIdx.y;
    int s = blockIdx.z;
    float vx = (s & 2) ? 1.f : -1.f;
    float vy = (s & 1) ? 1.f : -1.f;

    float gy = coord[((size_t)b * NPIX + n) * 2 + 0];
    float gx = coord[((size_t)b * NPIX + n) * 2 + 1];

    // hr nearest (H=W=256): iy = floor((gy+1)*H/2 - 0.5 + 0.5)
    int iyH = (int)floorf((gy + 1.f) * 128.f);
    int ixH = (int)floorf((gx + 1.f) * 128.f);
    bool vH = (iyH >= 0) && (iyH < 256) && (ixH >= 0) && (ixH < 256);
    int iyHc = min(max(iyH, 0), 255), ixHc = min(max(ixH, 0), 255);

    // lr nearest (h=w=64) at shifted coord
    float cy = gy + vx * (1.f / 64.f);
    float cx = gx + vy * (1.f / 64.f);
    int iyL = (int)floorf((cy + 1.f) * 32.f);
    int ixL = (int)floorf((cx + 1.f) * 32.f);
    bool vL = (iyL >= 0) && (iyL < 64) && (ixL >= 0) && (ixL < 64);
    int iyLc = min(max(iyL, 0), 63), ixLc = min(max(ixL, 0), 63);

    float qcy = vL ? (-1.f + 0.015625f + 0.03125f * (float)iyLc) : 0.f;
    float qcx = vL ? (-1.f + 0.015625f + 0.03125f * (float)ixLc) : 0.f;
    float rel0 = (gy - qcy) * 64.f;
    float rel1 = (gx - qcx) * 64.f;

    const size_t M = MROWS;
    size_t r = ((size_t)(s * BATCH + b) << 16) + (size_t)n;
    size_t hrbase = ((size_t)b * 128) * 65536 + (size_t)iyHc * 256 + ixHc;
    size_t lrbase = ((size_t)b * 128) * 4096 + (size_t)iyLc * 64 + ixLc;
    float fH = vH ? 1.f : 0.f;
    float fL = vL ? 1.f : 0.f;

    for (int c = 0; c < 128; c++) {
        float f = feat[lrbase + (size_t)c * 4096] * fL;
        float g = hr[hrbase + (size_t)c * 65536] * fH;
        float l = lr[lrbase + (size_t)c * 4096] * fL;
        X[(size_t)c * M + r]         = tf32r(f);
        X[(size_t)(128 + c) * M + r] = tf32r(g);
        X[(size_t)(256 + c) * M + r] = tf32r(g - l);
    }
    X[(size_t)384 * M + r] = tf32r(rel0);
    X[(size_t)385 * M + r] = tf32r(rel1);
#pragma unroll
    for (int k = 386; k < K1PAD; k++) X[(size_t)k * M + r] = 0.f;
}

// ---------------- tf32 GEMM: out[No, M] = act(W^T * in + b) ----------------
// in/out feature-major [K, M] / [No, M]; buffers split at feature 512 (lo->A, hi->B)
__global__ void __launch_bounds__(256, 2)
k_gemm(const float* __restrict__ inA, const float* __restrict__ inB,
       const float* __restrict__ W, const float* __restrict__ bias,
       float* __restrict__ outA, float* __restrict__ outB,
       int K, int No, int relu, int rnd) {
    constexpr int BK = 16, STRD = 136;
    __shared__ float As[2][BK * STRD];
    __shared__ float Bs[2][BK * STRD];
    __shared__ float bias_s[128];

    const size_t M = MROWS;
    int n0 = blockIdx.x * 128;
    size_t m0 = (size_t)blockIdx.y * 128;
    int tid = threadIdx.x;
    int w = tid >> 5, lane = tid & 31;
    int gid = lane >> 2, ctid = lane & 3;
    int warp_m = (w & 1) * 64;
    int warp_n = (w >> 1) * 32;

    if (tid < 128) bias_s[tid] = bias[n0 + tid];

    float acc[4][4][4];
#pragma unroll
    for (int a = 0; a < 4; a++)
#pragma unroll
        for (int bq = 0; bq < 4; bq++)
#pragma unroll
            for (int c = 0; c < 4; c++) acc[a][bq][c] = 0.f;

    int KT = K / BK;

    // prologue: tile 0 -> buf 0
    {
        const float* Ain = inA;  // k0 = 0 always < 512
        const float* Win = W + (size_t)0 * No + n0;
#pragma unroll
        for (int i = tid; i < 512; i += 256) {
            int kk = i >> 5, c4 = (i & 31) << 2;
            cpasync16(&As[0][kk * STRD + c4], Ain + (size_t)kk * M + m0 + c4);
        }
#pragma unroll
        for (int i = tid; i < 512; i += 256) {
            int kk = i >> 5, c4 = (i & 31) << 2;
            cpasync16(&Bs[0][kk * STRD + c4], Win + (size_t)kk * No + c4);
        }
        asm volatile("cp.async.commit_group;\n" ::);
    }

    for (int kt = 0; kt < KT; kt++) {
        int cur = kt & 1;
        if (kt + 1 < KT) {
            int k0 = (kt + 1) * BK;
            const float* Ain = (k0 >= 512) ? (inB + (size_t)(k0 - 512) * M)
                                           : (inA + (size_t)k0 * M);
            const float* Win = W + (size_t)k0 * No + n0;
            int nxt = cur ^ 1;
#pragma unroll
            for (int i = tid; i < 512; i += 256) {
                int kk = i >> 5, c4 = (i & 31) << 2;
                cpasync16(&As[nxt][kk * STRD + c4], Ain + (size_t)kk * M + m0 + c4);
            }
#pragma unroll
            for (int i = tid; i < 512; i += 256) {
                int kk = i >> 5, c4 = (i & 31) << 2;
                cpasync16(&Bs[nxt][kk * STRD + c4], Win + (size_t)kk * No + c4);
            }
            asm volatile("cp.async.commit_group;\n" ::);
            asm volatile("cp.async.wait_group 1;\n" ::);
        } else {
            asm volatile("cp.async.wait_group 0;\n" ::);
        }
        __syncthreads();

#pragma unroll
        for (int kk = 0; kk < 16; kk += 8) {
            uint32_t afr[4][4], bfr[4][2];
            const float* Ab = &As[cur][(kk + ctid) * STRD];
#pragma unroll
            for (int mt = 0; mt < 4; mt++) {
                int m = warp_m + mt * 16 + gid;
                afr[mt][0] = __float_as_uint(Ab[m]);
                afr[mt][1] = __float_as_uint(Ab[m + 8]);
                afr[mt][2] = __float_as_uint(Ab[4 * STRD + m]);
                afr[mt][3] = __float_as_uint(Ab[4 * STRD + m + 8]);
            }
            const float* Bb = &Bs[cur][(kk + ctid) * STRD];
#pragma unroll
            for (int nt = 0; nt < 4; nt++) {
                int nn = warp_n + nt * 8 + gid;
                bfr[nt][0] = __float_as_uint(Bb[nn]);
                bfr[nt][1] = __float_as_uint(Bb[4 * STRD + nn]);
            }
#pragma unroll
            for (int mt = 0; mt < 4; mt++)
#pragma unroll
                for (int nt = 0; nt < 4; nt++)
                    mma_tf32(acc[mt][nt], afr[mt], bfr[nt]);
        }
        __syncthreads();
    }

    // epilogue
    float* OB = (n0 >= 512) ? outB : outA;
    int nb = (n0 >= 512) ? (n0 - 512) : n0;
#pragma unroll
    for (int mt = 0; mt < 4; mt++) {
        size_t mg = m0 + (size_t)(warp_m + mt * 16 + gid);
#pragma unroll
        for (int nt = 0; nt < 4; nt++) {
            int j = warp_n + nt * 8 + 2 * ctid;
            float v0 = acc[mt][nt][0] + bias_s[j];
            float v1 = acc[mt][nt][1] + bias_s[j + 1];
            float v2 = acc[mt][nt][2] + bias_s[j];
            float v3 = acc[mt][nt][3] + bias_s[j + 1];
            if (relu) {
                v0 = fmaxf(v0, 0.f); v1 = fmaxf(v1, 0.f);
                v2 = fmaxf(v2, 0.f); v3 = fmaxf(v3, 0.f);
            }
            if (rnd) {
                v0 = tf32r(v0); v1 = tf32r(v1);
                v2 = tf32r(v2); v3 = tf32r(v3);
            }
            OB[(size_t)(nb + j) * M + mg]         = v0;
            OB[(size_t)(nb + j + 1) * M + mg]     = v1;
            OB[(size_t)(nb + j) * M + mg + 8]     = v2;
            OB[(size_t)(nb + j + 1) * M + mg + 8] = v3;
        }
    }
}

// ---------------- layer 5 + softmax combine ----------------
__global__ void k_combine(const float* __restrict__ act,  // [128, M]
                          const float* __restrict__ w5,   // [128, 2]
                          const float* __restrict__ b5,   // [2]
                          float* __restrict__ out) {
    __shared__ float ws[256];
    int tid = threadIdx.x;
    ws[tid] = w5[tid];
    __syncthreads();

    int p = blockIdx.x * 256 + tid;
    int b = blockIdx.y;
    const size_t M = MROWS;

    float p0[4], p1[4];
#pragma unroll
    for (int s = 0; s < 4; s++) {
        size_t r = ((size_t)(s * BATCH + b) << 16) + (size_t)p;
        float a0 = b5[0], a1 = b5[1];
#pragma unroll 16
        for (int k = 0; k < 128; k++) {
            float v = act[(size_t)k * M + r];
            a0 = fmaf(v, ws[2 * k], a0);
            a1 = fmaf(v, ws[2 * k + 1], a1);
        }
        p0[s] = a0; p1[s] = a1;
    }
    float mx = fmaxf(fmaxf(p1[0], p1[1]), fmaxf(p1[2], p1[3]));
    float e0 = expf(p1[0] - mx), e1 = expf(p1[1] - mx);
    float e2 = expf(p1[2] - mx), e3 = expf(p1[3] - mx);
    float sum = e0 + e1 + e2 + e3;
    float ret = (p0[0] * e0 + p0[1] * e1 + p0[2] * e2 + p0[3] * e3) / sum;
    out[(size_t)b * NPIX + p] = ret;
}

// ---------------- launch ----------------
extern "C" void kernel_launch(void* const* d_in, const int* in_sizes, int n_in,
                              void* d_out, int out_size) {
    const float* feat  = (const float*)d_in[0];
    const float* coord = (const float*)d_in[1];
    const float* hr    = (const float*)d_in[2];
    const float* lr    = (const float*)d_in[3];
    const float* w1 = (const float*)d_in[4];
    const float* b1 = (const float*)d_in[5];
    const float* w2 = (const float*)d_in[6];
    const float* b2 = (const float*)d_in[7];
    const float* w3 = (const float*)d_in[8];
    const float* b3 = (const float*)d_in[9];
    const float* w4 = (const float*)d_in[10];
    const float* b4 = (const float*)d_in[11];
    const float* w5 = (const float*)d_in[12];
    const float* b5 = (const float*)d_in[13];

    float *X, *A, *B, *Wb;
    cudaGetSymbolAddress((void**)&X,  g_X);
    cudaGetSymbolAddress((void**)&A,  g_bufA);
    cudaGetSymbolAddress((void**)&B,  g_bufB);
    cudaGetSymbolAddress((void**)&Wb, g_W);

    float* W1 = Wb;
    float* W2 = W1 + 400 * 1024;
    float* W3 = W2 + 1024 * 512;
    float* W4 = W3 + 512 * 256;

    k_prep<<<(400 * 1024 + 255) / 256, 256>>>(w1, W1, 386, 400, 1024);
    k_prep<<<(1024 * 512 + 255) / 256, 256>>>(w2, W2, 1024, 1024, 512);
    k_prep<<<(512 * 256 + 255) / 256, 256>>>(w3, W3, 512, 512, 256);
    k_prep<<<(256 * 128 + 255) / 256, 256>>>(w4, W4, 256, 256, 128);

    k_build<<<dim3(256, 2, 4), 256>>>(feat, coord, hr, lr, X);

    // L1: X[400,M] -> act1[1024,M] split across A (lo 512) / B (hi 512)
    k_gemm<<<dim3(8, 4096), 256>>>(X, X, W1, b1, A, B, 400, 1024, 1, 1);
    // L2: act1[1024,M] -> act2[512,M] in X
    k_gemm<<<dim3(4, 4096), 256>>>(A, B, W2, b2, X, X, 1024, 512, 1, 1);
    // L3: act2[512,M] -> act3[256,M] in A
    k_gemm<<<dim3(2, 4096), 256>>>(X, X, W3, b3, A, A, 512, 256, 1, 1);
    // L4: act3[256,M] -> act4[128,M] in B (fp32 out, no rounding)
    k_gemm<<<dim3(1, 4096), 256>>>(A, A, W4, b4, B, B, 256, 128, 1, 0);

    k_combine<<<dim3(256, 2), 256>>>(B, w5, b5, (float*)d_out);
}

// round 5
// speedup vs baseline: 1.0817x; 1.0817x over previous
#include <cuda_runtime.h>
#include <cstdint>

// Problem constants
#define NPIX   65536        // H*W = 256*256
#define BATCH  2
#define MROWS  524288       // 4 shifts * BATCH * NPIX
#define K1PAD  400          // 386 padded to multiple of 16

// Static scratch (each < 2GB). Feature-major activations [K, M].
__device__ float g_X[512u * 524288u];     // X / act2 buffer
__device__ float g_bufA[512u * 524288u];  // act1 lo / act3
__device__ float g_bufB[512u * 524288u];  // act1 hi / act4
__device__ float g_W[1097728];            // tf32-rounded padded weights

// ---------------- helpers ----------------
__device__ __forceinline__ float tf32r(float x) {
    uint32_t u;
    asm("cvt.rna.tf32.f32 %0, %1;" : "=r"(u) : "f"(x));
    return __uint_as_float(u);
}

__device__ __forceinline__ void mma_tf32(float c[4], const uint32_t a[4], const uint32_t b[2]) {
    asm volatile(
        "mma.sync.aligned.m16n8k8.row.col.f32.tf32.tf32.f32 "
        "{%0,%1,%2,%3}, {%4,%5,%6,%7}, {%8,%9}, {%0,%1,%2,%3};\n"
        : "+f"(c[0]), "+f"(c[1]), "+f"(c[2]), "+f"(c[3])
        : "r"(a[0]), "r"(a[1]), "r"(a[2]), "r"(a[3]), "r"(b[0]), "r"(b[1]));
}

__device__ __forceinline__ void cpasync16(void* smem, const void* gmem) {
    uint32_t s = (uint32_t)__cvta_generic_to_shared(smem);
    asm volatile("cp.async.cg.shared.global [%0], [%1], 16;\n" :: "r"(s), "l"(gmem));
}

// ---------------- weight prep: pad K and round to tf32 ----------------
__global__ void k_prep(const float* __restrict__ w, float* __restrict__ dst,
                       int Ksrc, int Kdst, int No) {
    int i = blockIdx.x * 256 + threadIdx.x;
    int total = Kdst * No;
    if (i >= total) return;
    int k = i / No;
    int j = i - k * No;
    float v = (k < Ksrc) ? w[(size_t)k * No + j] : 0.f;
    dst[i] = tf32r(v);
}

// ---------------- build X [400, M] feature-major, tf32-rounded ----------------
__global__ void k_build(const float* __restrict__ feat, const float* __restrict__ coord,
                        const float* __restrict__ hr, const float* __restrict__ lr,
                        float* __restrict__ X) {
    int n = blockIdx.x * 256 + threadIdx.x;
    int b = blockIdx.y;
    int s = blockIdx.z;
    float vx = (s & 2) ? 1.f : -1.f;
    float vy = (s & 1) ? 1.f : -1.f;

    float gy = coord[((size_t)b * NPIX + n) * 2 + 0];
    float gx = coord[((size_t)b * NPIX + n) * 2 + 1];

    int iyH = (int)floorf((gy + 1.f) * 128.f);
    int ixH = (int)floorf((gx + 1.f) * 128.f);
    bool vH = (iyH >= 0) && (iyH < 256) && (ixH >= 0) && (ixH < 256);
    int iyHc = min(max(iyH, 0), 255), ixHc = min(max(ixH, 0), 255);

    float cy = gy + vx * (1.f / 64.f);
    float cx = gx + vy * (1.f / 64.f);
    int iyL = (int)floorf((cy + 1.f) * 32.f);
    int ixL = (int)floorf((cx + 1.f) * 32.f);
    bool vL = (iyL >= 0) && (iyL < 64) && (ixL >= 0) && (ixL < 64);
    int iyLc = min(max(iyL, 0), 63), ixLc = min(max(ixL, 0), 63);

    float qcy = vL ? (-1.f + 0.015625f + 0.03125f * (float)iyLc) : 0.f;
    float qcx = vL ? (-1.f + 0.015625f + 0.03125f * (float)ixLc) : 0.f;
    float rel0 = (gy - qcy) * 64.f;
    float rel1 = (gx - qcx) * 64.f;

    const size_t M = MROWS;
    size_t r = ((size_t)(s * BATCH + b) << 16) + (size_t)n;
    size_t hrbase = ((size_t)b * 128) * 65536 + (size_t)iyHc * 256 + ixHc;
    size_t lrbase = ((size_t)b * 128) * 4096 + (size_t)iyLc * 64 + ixLc;
    float fH = vH ? 1.f : 0.f;
    float fL = vL ? 1.f : 0.f;

    for (int c = 0; c < 128; c++) {
        float f = feat[lrbase + (size_t)c * 4096] * fL;
        float g = hr[hrbase + (size_t)c * 65536] * fH;
        float l = lr[lrbase + (size_t)c * 4096] * fL;
        X[(size_t)c * M + r]         = tf32r(f);
        X[(size_t)(128 + c) * M + r] = tf32r(g);
        X[(size_t)(256 + c) * M + r] = tf32r(g - l);
    }
    X[(size_t)384 * M + r] = tf32r(rel0);
    X[(size_t)385 * M + r] = tf32r(rel1);
#pragma unroll
    for (int k = 386; k < K1PAD; k++) X[(size_t)k * M + r] = 0.f;
}

// ---------------- tf32 GEMM: out[No, M] = act(W^T * in + b) ----------------
// 128x128 CTA tile, 4 warps, each warp 64(m) x 64(n).
// in/out feature-major [K, M] / [No, M]; buffers split at feature 512 (lo->A, hi->B)
__global__ void __launch_bounds__(128, 2)
k_gemm(const float* __restrict__ inA, const float* __restrict__ inB,
       const float* __restrict__ W, const float* __restrict__ bias,
       float* __restrict__ outA, float* __restrict__ outB,
       int K, int No, int relu, int rnd) {
    constexpr int BK = 16, STRD = 136;
    __shared__ float As[2][BK * STRD];
    __shared__ float Bs[2][BK * STRD];
    __shared__ float bias_s[128];

    const size_t M = MROWS;
    int n0 = blockIdx.x * 128;
    size_t m0 = (size_t)blockIdx.y * 128;
    int tid = threadIdx.x;
    int w = tid >> 5, lane = tid & 31;
    int gid = lane >> 2, ctid = lane & 3;
    int warp_m = (w & 1) * 64;
    int warp_n = (w >> 1) * 64;

    bias_s[tid] = bias[n0 + tid];

    float acc[4][8][4];
#pragma unroll
    for (int a = 0; a < 4; a++)
#pragma unroll
        for (int bq = 0; bq < 8; bq++)
#pragma unroll
            for (int c = 0; c < 4; c++) acc[a][bq][c] = 0.f;

    int KT = K / BK;

    // prologue: tile 0 -> buf 0
    {
        const float* Ain = inA;  // k0 = 0 always < 512
        const float* Win = W + (size_t)0 * No + n0;
#pragma unroll
        for (int i = tid; i < 512; i += 128) {
            int kk = i >> 5, c4 = (i & 31) << 2;
            cpasync16(&As[0][kk * STRD + c4], Ain + (size_t)kk * M + m0 + c4);
        }
#pragma unroll
        for (int i = tid; i < 512; i += 128) {
            int kk = i >> 5, c4 = (i & 31) << 2;
            cpasync16(&Bs[0][kk * STRD + c4], Win + (size_t)kk * No + c4);
        }
        asm volatile("cp.async.commit_group;\n" ::);
    }

    for (int kt = 0; kt < KT; kt++) {
        int cur = kt & 1;
        if (kt + 1 < KT) {
            int k0 = (kt + 1) * BK;
            const float* Ain = (k0 >= 512) ? (inB + (size_t)(k0 - 512) * M)
                                           : (inA + (size_t)k0 * M);
            const float* Win = W + (size_t)k0 * No + n0;
            int nxt = cur ^ 1;
#pragma unroll
            for (int i = tid; i < 512; i += 128) {
                int kk = i >> 5, c4 = (i & 31) << 2;
                cpasync16(&As[nxt][kk * STRD + c4], Ain + (size_t)kk * M + m0 + c4);
            }
#pragma unroll
            for (int i = tid; i < 512; i += 128) {
                int kk = i >> 5, c4 = (i & 31) << 2;
                cpasync16(&Bs[nxt][kk * STRD + c4], Win + (size_t)kk * No + c4);
            }
            asm volatile("cp.async.commit_group;\n" ::);
            asm volatile("cp.async.wait_group 1;\n" ::);
        } else {
            asm volatile("cp.async.wait_group 0;\n" ::);
        }
        __syncthreads();

#pragma unroll
        for (int kk = 0; kk < 16; kk += 8) {
            uint32_t afr[4][4], bfr[8][2];
            const float* Ab = &As[cur][(kk + ctid) * STRD];
#pragma unroll
            for (int mt = 0; mt < 4; mt++) {
                int m = warp_m + mt * 16 + gid;
                afr[mt][0] = __float_as_uint(Ab[m]);
                afr[mt][1] = __float_as_uint(Ab[m + 8]);
                afr[mt][2] = __float_as_uint(Ab[4 * STRD + m]);
                afr[mt][3] = __float_as_uint(Ab[4 * STRD + m + 8]);
            }
            const float* Bb = &Bs[cur][(kk + ctid) * STRD];
#pragma unroll
            for (int nt = 0; nt < 8; nt++) {
                int nn = warp_n + nt * 8 + gid;
                bfr[nt][0] = __float_as_uint(Bb[nn]);
                bfr[nt][1] = __float_as_uint(Bb[4 * STRD + nn]);
            }
#pragma unroll
            for (int mt = 0; mt < 4; mt++)
#pragma unroll
                for (int nt = 0; nt < 8; nt++)
                    mma_tf32(acc[mt][nt], afr[mt], bfr[nt]);
        }
        __syncthreads();
    }

    // epilogue
    float* OB = (n0 >= 512) ? outB : outA;
    int nb = (n0 >= 512) ? (n0 - 512) : n0;
#pragma unroll
    for (int mt = 0; mt < 4; mt++) {
        size_t mg = m0 + (size_t)(warp_m + mt * 16 + gid);
#pragma unroll
        for (int nt = 0; nt < 8; nt++) {
            int j = warp_n + nt * 8 + 2 * ctid;
            float v0 = acc[mt][nt][0] + bias_s[j];
            float v1 = acc[mt][nt][1] + bias_s[j + 1];
            float v2 = acc[mt][nt][2] + bias_s[j];
            float v3 = acc[mt][nt][3] + bias_s[j + 1];
            if (relu) {
                v0 = fmaxf(v0, 0.f); v1 = fmaxf(v1, 0.f);
                v2 = fmaxf(v2, 0.f); v3 = fmaxf(v3, 0.f);
            }
            if (rnd) {
                v0 = tf32r(v0); v1 = tf32r(v1);
                v2 = tf32r(v2); v3 = tf32r(v3);
            }
            OB[(size_t)(nb + j) * M + mg]         = v0;
            OB[(size_t)(nb + j + 1) * M + mg]     = v1;
            OB[(size_t)(nb + j) * M + mg + 8]     = v2;
            OB[(size_t)(nb + j + 1) * M + mg + 8] = v3;
        }
    }
}

// ---------------- layer 5 + softmax combine ----------------
__global__ void k_combine(const float* __restrict__ act,  // [128, M]
                          const float* __restrict__ w5,   // [128, 2]
                          const float* __restrict__ b5,   // [2]
                          float* __restrict__ out) {
    __shared__ float ws[256];
    int tid = threadIdx.x;
    ws[tid] = w5[tid];
    __syncthreads();

    int p = blockIdx.x * 256 + tid;
    int b = blockIdx.y;
    const size_t M = MROWS;

    float p0[4], p1[4];
#pragma unroll
    for (int s = 0; s < 4; s++) {
        size_t r = ((size_t)(s * BATCH + b) << 16) + (size_t)p;
        float a0 = b5[0], a1 = b5[1];
#pragma unroll 16
        for (int k = 0; k < 128; k++) {
            float v = act[(size_t)k * M + r];
            a0 = fmaf(v, ws[2 * k], a0);
            a1 = fmaf(v, ws[2 * k + 1], a1);
        }
        p0[s] = a0; p1[s] = a1;
    }
    float mx = fmaxf(fmaxf(p1[0], p1[1]), fmaxf(p1[2], p1[3]));
    float e0 = expf(p1[0] - mx), e1 = expf(p1[1] - mx);
    float e2 = expf(p1[2] - mx), e3 = expf(p1[3] - mx);
    float sum = e0 + e1 + e2 + e3;
    float ret = (p0[0] * e0 + p0[1] * e1 + p0[2] * e2 + p0[3] * e3) / sum;
    out[(size_t)b * NPIX + p] = ret;
}

// ---------------- launch ----------------
extern "C" void kernel_launch(void* const* d_in, const int* in_sizes, int n_in,
                              void* d_out, int out_size) {
    const float* feat  = (const float*)d_in[0];
    const float* coord = (const float*)d_in[1];
    const float* hr    = (const float*)d_in[2];
    const float* lr    = (const float*)d_in[3];
    const float* w1 = (const float*)d_in[4];
    const float* b1 = (const float*)d_in[5];
    const float* w2 = (const float*)d_in[6];
    const float* b2 = (const float*)d_in[7];
    const float* w3 = (const float*)d_in[8];
    const float* b3 = (const float*)d_in[9];
    const float* w4 = (const float*)d_in[10];
    const float* b4 = (const float*)d_in[11];
    const float* w5 = (const float*)d_in[12];
    const float* b5 = (const float*)d_in[13];

    float *X, *A, *B, *Wb;
    cudaGetSymbolAddress((void**)&X,  g_X);
    cudaGetSymbolAddress((void**)&A,  g_bufA);
    cudaGetSymbolAddress((void**)&B,  g_bufB);
    cudaGetSymbolAddress((void**)&Wb, g_W);

    float* W1 = Wb;
    float* W2 = W1 + 400 * 1024;
    float* W3 = W2 + 1024 * 512;
    float* W4 = W3 + 512 * 256;

    k_prep<<<(400 * 1024 + 255) / 256, 256>>>(w1, W1, 386, 400, 1024);
    k_prep<<<(1024 * 512 + 255) / 256, 256>>>(w2, W2, 1024, 1024, 512);
    k_prep<<<(512 * 256 + 255) / 256, 256>>>(w3, W3, 512, 512, 256);
    k_prep<<<(256 * 128 + 255) / 256, 256>>>(w4, W4, 256, 256, 128);

    k_build<<<dim3(256, 2, 4), 256>>>(feat, coord, hr, lr, X);

    // L1: X[400,M] -> act1[1024,M] split across A (lo 512) / B (hi 512)
    k_gemm<<<dim3(8, 4096), 128>>>(X, X, W1, b1, A, B, 400, 1024, 1, 1);
    // L2: act1[1024,M] -> act2[512,M] in X
    k_gemm<<<dim3(4, 4096), 128>>>(A, B, W2, b2, X, X, 1024, 512, 1, 1);
    // L3: act2[512,M] -> act3[256,M] in A
    k_gemm<<<dim3(2, 4096), 128>>>(X, X, W3, b3, A, A, 512, 256, 1, 1);
    // L4: act3[256,M] -> act4[128,M] in B (fp32 out, no rounding)
    k_gemm<<<dim3(1, 4096), 128>>>(A, A, W4, b4, B, B, 256, 128, 1, 0);

    k_combine<<<dim3(256, 2), 256>>>(B, w5, b5, (float*)d_out);
}

// round 6
// speedup vs baseline: 2.0987x; 1.9402x over previous
#include <cuda_runtime.h>
#include <cuda_fp16.h>
#include <cstdint>

// Problem constants
#define NPIX   65536        // H*W = 256*256
#define BATCH  2
#define MROWS  524288       // 4 shifts * BATCH * NPIX
#define KW1    208          // 416 halves (386 padded) -> 208 packed words

// Static scratch. Packed half2 activations, word layout [K/2][M].
// g_B1: X (208 rows) / act2 (256 rows) / act4-as-fp32 (128 float rows)
// g_A : act1 (512 rows) / act3 (128 rows)
__device__ uint32_t g_B1[256u * 524288u];   // 536 MB
__device__ uint32_t g_A[512u * 524288u];    // 1073 MB
__device__ uint32_t g_W[557056];            // packed fp16 weights [K/2][No]

// ---------------- helpers ----------------
__device__ __forceinline__ void mma_f16(float c[4], const uint32_t a[4], const uint32_t b[2]) {
    asm volatile(
        "mma.sync.aligned.m16n8k16.row.col.f32.f16.f16.f32 "
        "{%0,%1,%2,%3}, {%4,%5,%6,%7}, {%8,%9}, {%0,%1,%2,%3};\n"
        : "+f"(c[0]), "+f"(c[1]), "+f"(c[2]), "+f"(c[3])
        : "r"(a[0]), "r"(a[1]), "r"(a[2]), "r"(a[3]), "r"(b[0]), "r"(b[1]));
}

__device__ __forceinline__ void cpasync16(void* smem, const void* gmem) {
    uint32_t s = (uint32_t)__cvta_generic_to_shared(smem);
    asm volatile("cp.async.cg.shared.global [%0], [%1], 16;\n" :: "r"(s), "l"(gmem));
}

__device__ __forceinline__ uint32_t packh2(float a, float b) {
    __half2 h = __floats2half2_rn(a, b);   // low = a, high = b
    return *(uint32_t*)&h;
}

// ---------------- weight prep: pack fp16 pairs [K/2][No] ----------------
__global__ void k_prep(const float* __restrict__ w, uint32_t* __restrict__ dst,
                       int Ksrc, int KW, int No) {
    int i = blockIdx.x * 256 + threadIdx.x;
    if (i >= KW * No) return;
    int kk = i / No;
    int j = i - kk * No;
    int k0 = 2 * kk, k1 = 2 * kk + 1;
    float v0 = (k0 < Ksrc) ? w[(size_t)k0 * No + j] : 0.f;
    float v1 = (k1 < Ksrc) ? w[(size_t)k1 * No + j] : 0.f;
    dst[i] = packh2(v0, v1);
}

// ---------------- build X [208][M] packed words ----------------
__global__ void k_build(const float* __restrict__ feat, const float* __restrict__ coord,
                        const float* __restrict__ hr, const float* __restrict__ lr,
                        uint32_t* __restrict__ X) {
    int n = blockIdx.x * 256 + threadIdx.x;
    int b = blockIdx.y;
    int s = blockIdx.z;
    float vx = (s & 2) ? 1.f : -1.f;
    float vy = (s & 1) ? 1.f : -1.f;

    float gy = coord[((size_t)b * NPIX + n) * 2 + 0];
    float gx = coord[((size_t)b * NPIX + n) * 2 + 1];

    int iyH = (int)floorf((gy + 1.f) * 128.f);
    int ixH = (int)floorf((gx + 1.f) * 128.f);
    bool vH = (iyH >= 0) && (iyH < 256) && (ixH >= 0) && (ixH < 256);
    int iyHc = min(max(iyH, 0), 255), ixHc = min(max(ixH, 0), 255);

    float cy = gy + vx * (1.f / 64.f);
    float cx = gx + vy * (1.f / 64.f);
    int iyL = (int)floorf((cy + 1.f) * 32.f);
    int ixL = (int)floorf((cx + 1.f) * 32.f);
    bool vL = (iyL >= 0) && (iyL < 64) && (ixL >= 0) && (ixL < 64);
    int iyLc = min(max(iyL, 0), 63), ixLc = min(max(ixL, 0), 63);

    float qcy = vL ? (-1.f + 0.015625f + 0.03125f * (float)iyLc) : 0.f;
    float qcx = vL ? (-1.f + 0.015625f + 0.03125f * (float)ixLc) : 0.f;
    float rel0 = (gy - qcy) * 64.f;
    float rel1 = (gx - qcx) * 64.f;

    const size_t M = MROWS;
    size_t r = ((size_t)(s * BATCH + b) << 16) + (size_t)n;
    size_t hrbase = ((size_t)b * 128) * 65536 + (size_t)iyHc * 256 + ixHc;
    size_t lrbase = ((size_t)b * 128) * 4096 + (size_t)iyLc * 64 + ixLc;
    float fH = vH ? 1.f : 0.f;
    float fL = vL ? 1.f : 0.f;

    // words 0..63: feat pairs
    for (int kk = 0; kk < 64; kk++) {
        int c = 2 * kk;
        float f0 = feat[lrbase + (size_t)c * 4096] * fL;
        float f1 = feat[lrbase + (size_t)(c + 1) * 4096] * fL;
        X[(size_t)kk * M + r] = packh2(f0, f1);
    }
    // words 64..127: hr pairs
    for (int kk = 64; kk < 128; kk++) {
        int c = 2 * kk - 128;
        float g0 = hr[hrbase + (size_t)c * 65536] * fH;
        float g1 = hr[hrbase + (size_t)(c + 1) * 65536] * fH;
        X[(size_t)kk * M + r] = packh2(g0, g1);
    }
    // words 128..191: (hr - lr) pairs
    for (int kk = 128; kk < 192; kk++) {
        int c = 2 * kk - 256;
        float g0 = hr[hrbase + (size_t)c * 65536] * fH;
        float g1 = hr[hrbase + (size_t)(c + 1) * 65536] * fH;
        float l0 = lr[lrbase + (size_t)c * 4096] * fL;
        float l1 = lr[lrbase + (size_t)(c + 1) * 4096] * fL;
        X[(size_t)kk * M + r] = packh2(g0 - l0, g1 - l1);
    }
    // word 192: rel coords; 193..207: zero pad
    X[(size_t)192 * M + r] = packh2(rel0, rel1);
#pragma unroll
    for (int kk = 193; kk < KW1; kk++) X[(size_t)kk * M + r] = 0u;
}

// ---------------- fp16 GEMM: out[No, M] = act(W^T * in + b) ----------------
// 128x128 CTA tile, 4 warps, each warp 64(m) x 64(n). BK = 32 halves = 16 word rows.
// in: packed [KW][M]; W: packed [KW][No]; out16 packed [No/2][M] or out32 float [No][M].
__global__ void __launch_bounds__(128, 2)
k_gemm(const uint32_t* __restrict__ in, const uint32_t* __restrict__ W,
       const float* __restrict__ bias, uint32_t* __restrict__ out16,
       float* __restrict__ out32, int KW, int No, int relu, int pack16) {
    constexpr int STRD = 136;
    __shared__ uint32_t As[2][16 * STRD];
    __shared__ uint32_t Bs[2][16 * STRD];
    __shared__ float bias_s[128];

    const size_t M = MROWS;
    int n0 = blockIdx.x * 128;
    size_t m0 = (size_t)blockIdx.y * 128;
    int tid = threadIdx.x;
    int w = tid >> 5, lane = tid & 31;
    int gid = lane >> 2, ctid = lane & 3;
    int warp_m = (w & 1) * 64;
    int warp_n = (w >> 1) * 64;

    bias_s[tid] = bias[n0 + tid];

    float acc[4][8][4];
#pragma unroll
    for (int a = 0; a < 4; a++)
#pragma unroll
        for (int bq = 0; bq < 8; bq++)
#pragma unroll
            for (int c = 0; c < 4; c++) acc[a][bq][c] = 0.f;

    int KT = KW >> 4;   // chunks of 16 word rows

    // prologue: chunk 0 -> buf 0
    {
#pragma unroll
        for (int i = tid; i < 512; i += 128) {
            int kk = i >> 5, c4 = (i & 31) << 2;
            cpasync16(&As[0][kk * STRD + c4], in + (size_t)kk * M + m0 + c4);
        }
#pragma unroll
        for (int i = tid; i < 512; i += 128) {
            int kk = i >> 5, c4 = (i & 31) << 2;
            cpasync16(&Bs[0][kk * STRD + c4], W + (size_t)kk * No + n0 + c4);
        }
        asm volatile("cp.async.commit_group;\n" ::);
    }

    for (int kt = 0; kt < KT; kt++) {
        int cur = kt & 1;
        if (kt + 1 < KT) {
            int kw0 = (kt + 1) * 16;
            int nxt = cur ^ 1;
#pragma unroll
            for (int i = tid; i < 512; i += 128) {
                int kk = i >> 5, c4 = (i & 31) << 2;
                cpasync16(&As[nxt][kk * STRD + c4],
                          in + (size_t)(kw0 + kk) * M + m0 + c4);
            }
#pragma unroll
            for (int i = tid; i < 512; i += 128) {
                int kk = i >> 5, c4 = (i & 31) << 2;
                cpasync16(&Bs[nxt][kk * STRD + c4],
                          W + (size_t)(kw0 + kk) * No + n0 + c4);
            }
            asm volatile("cp.async.commit_group;\n" ::);
            asm volatile("cp.async.wait_group 1;\n" ::);
        } else {
            asm volatile("cp.async.wait_group 0;\n" ::);
        }
        __syncthreads();

        // two k16 slices per chunk; slice s uses word rows s*8 + {ctid, ctid+4}
#pragma unroll
        for (int s8 = 0; s8 < 16; s8 += 8) {
            uint32_t afr[4][4], bfr[8][2];
            const uint32_t* Ab = &As[cur][(s8 + ctid) * STRD];
#pragma unroll
            for (int mt = 0; mt < 4; mt++) {
                int m = warp_m + mt * 16 + gid;
                afr[mt][0] = Ab[m];
                afr[mt][1] = Ab[m + 8];
                afr[mt][2] = Ab[4 * STRD + m];
                afr[mt][3] = Ab[4 * STRD + m + 8];
            }
            const uint32_t* Bb = &Bs[cur][(s8 + ctid) * STRD];
#pragma unroll
            for (int nt = 0; nt < 8; nt++) {
                int nn = warp_n + nt * 8 + gid;
                bfr[nt][0] = Bb[nn];
                bfr[nt][1] = Bb[4 * STRD + nn];
            }
#pragma unroll
            for (int mt = 0; mt < 4; mt++)
#pragma unroll
                for (int nt = 0; nt < 8; nt++)
                    mma_f16(acc[mt][nt], afr[mt], bfr[nt]);
        }
        __syncthreads();
    }

    // epilogue
#pragma unroll
    for (int mt = 0; mt < 4; mt++) {
        size_t mg = m0 + (size_t)(warp_m + mt * 16 + gid);
#pragma unroll
        for (int nt = 0; nt < 8; nt++) {
            int j = warp_n + nt * 8 + 2 * ctid;
            float v0 = acc[mt][nt][0] + bias_s[j];
            float v1 = acc[mt][nt][1] + bias_s[j + 1];
            float v2 = acc[mt][nt][2] + bias_s[j];
            float v3 = acc[mt][nt][3] + bias_s[j + 1];
            if (relu) {
                v0 = fmaxf(v0, 0.f); v1 = fmaxf(v1, 0.f);
                v2 = fmaxf(v2, 0.f); v3 = fmaxf(v3, 0.f);
            }
            if (pack16) {
                int nn = ((n0 + j) >> 1);   // output word row
                out16[(size_t)nn * M + mg]     = packh2(v0, v1);
                out16[(size_t)nn * M + mg + 8] = packh2(v2, v3);
            } else {
                out32[(size_t)(n0 + j) * M + mg]         = v0;
                out32[(size_t)(n0 + j + 1) * M + mg]     = v1;
                out32[(size_t)(n0 + j) * M + mg + 8]     = v2;
                out32[(size_t)(n0 + j + 1) * M + mg + 8] = v3;
            }
        }
    }
}

// ---------------- layer 5 + softmax combine (act4 fp32 [128][M]) ----------------
__global__ void k_combine(const float* __restrict__ act,
                          const float* __restrict__ w5, const float* __restrict__ b5,
                          float* __restrict__ out) {
    __shared__ float ws[256];
    int tid = threadIdx.x;
    ws[tid] = w5[tid];
    __syncthreads();

    int p = blockIdx.x * 256 + tid;
    int b = blockIdx.y;
    const size_t M = MROWS;

    float p0[4], p1[4];
#pragma unroll
    for (int s = 0; s < 4; s++) {
        size_t r = ((size_t)(s * BATCH + b) << 16) + (size_t)p;
        float a0 = b5[0], a1 = b5[1];
#pragma unroll 16
        for (int k = 0; k < 128; k++) {
            float v = act[(size_t)k * M + r];
            a0 = fmaf(v, ws[2 * k], a0);
            a1 = fmaf(v, ws[2 * k + 1], a1);
        }
        p0[s] = a0; p1[s] = a1;
    }
    float mx = fmaxf(fmaxf(p1[0], p1[1]), fmaxf(p1[2], p1[3]));
    float e0 = expf(p1[0] - mx), e1 = expf(p1[1] - mx);
    float e2 = expf(p1[2] - mx), e3 = expf(p1[3] - mx);
    float sum = e0 + e1 + e2 + e3;
    float ret = (p0[0] * e0 + p0[1] * e1 + p0[2] * e2 + p0[3] * e3) / sum;
    out[(size_t)b * NPIX + p] = ret;
}

// ---------------- launch ----------------
extern "C" void kernel_launch(void* const* d_in, const int* in_sizes, int n_in,
                              void* d_out, int out_size) {
    const float* feat  = (const float*)d_in[0];
    const float* coord = (const float*)d_in[1];
    const float* hr    = (const float*)d_in[2];
    const float* lr    = (const float*)d_in[3];
    const float* w1 = (const float*)d_in[4];
    const float* b1 = (const float*)d_in[5];
    const float* w2 = (const float*)d_in[6];
    const float* b2 = (const float*)d_in[7];
    const float* w3 = (const float*)d_in[8];
    const float* b3 = (const float*)d_in[9];
    const float* w4 = (const float*)d_in[10];
    const float* b4 = (const float*)d_in[11];
    const float* w5 = (const float*)d_in[12];
    const float* b5 = (const float*)d_in[13];

    uint32_t *B1, *A, *Wb;
    cudaGetSymbolAddress((void**)&B1, g_B1);
    cudaGetSymbolAddress((void**)&A,  g_A);
    cudaGetSymbolAddress((void**)&Wb, g_W);

    uint32_t* W1 = Wb;                        // [208][1024]
    uint32_t* W2 = W1 + 208 * 1024;           // [512][512]
    uint32_t* W3 = W2 + 512 * 512;            // [256][256]
    uint32_t* W4 = W3 + 256 * 256;            // [128][128]

    k_prep<<<(208 * 1024 + 255) / 256, 256>>>(w1, W1, 386, 208, 1024);
    k_prep<<<(512 * 512 + 255) / 256, 256>>>(w2, W2, 1024, 512, 512);
    k_prep<<<(256 * 256 + 255) / 256, 256>>>(w3, W3, 512, 256, 256);
    k_prep<<<(128 * 128 + 255) / 256, 256>>>(w4, W4, 256, 128, 128);

    k_build<<<dim3(256, 2, 4), 256>>>(feat, coord, hr, lr, B1);

    // L1: X[208w,M] -> act1[512w,M] in A
    k_gemm<<<dim3(8, 4096), 128>>>(B1, W1, b1, A, nullptr, 208, 1024, 1, 1);
    // L2: act1 -> act2[256w,M] in B1
    k_gemm<<<dim3(4, 4096), 128>>>(A, W2, b2, B1, nullptr, 512, 512, 1, 1);
    // L3: act2 -> act3[128w,M] in A
    k_gemm<<<dim3(2, 4096), 128>>>(B1, W3, b3, A, nullptr, 256, 256, 1, 1);
    // L4: act3 -> act4 fp32 [128][M] in B1
    k_gemm<<<dim3(1, 4096), 128>>>(A, W4, b4, nullptr, (float*)B1, 128, 128, 1, 0);

    k_combine<<<dim3(256, 2), 256>>>((const float*)B1, w5, b5, (float*)d_out);
}